// round 1
// baseline (speedup 1.0000x reference)
#include <cuda_runtime.h>
#include <cstdint>

// Problem shape (fixed by the dataset):
//   encoded: [B=8, C=128, H=128, W=128] fp32
//   masks:   [B=8, M=16, H, W] int32 (0/1), channel 0 dropped
//   out:     [B, C, 15, 1] fp32 = masked spatial max per region
#define BB      8
#define CC      128
#define MMASKS  16
#define HWTOT   16384
#define NM      15
#define NCHUNK  64
#define CHUNK   (HWTOT / NCHUNK)   // 256 positions per CTA
#define TILE    32                 // positions per smem tile
#define NTILE   (CHUNK / TILE)     // 8
#define TPAD    33                 // pad to keep column LDS conflict-free

// Scratch (no allocations allowed): packed mask bits + order-mapped accumulators
__device__ unsigned int g_bits[BB * HWTOT];        // 512 KiB
__device__ unsigned int g_acc[BB * CC * NM];       // 60 KiB

// Monotonic fp32 <-> uint32 order mapping (so atomicMax works on floats).
__device__ __forceinline__ unsigned int f2ord(float f) {
    unsigned int u = __float_as_uint(f);
    return (u & 0x80000000u) ? ~u : (u | 0x80000000u);
}
__device__ __forceinline__ float ord2f(unsigned int u) {
    unsigned int v = (u & 0x80000000u) ? (u ^ 0x80000000u) : ~u;
    return __uint_as_float(v);
}
#define ORD_NEGINF 0x007FFFFFu   // f2ord(-inf)

// ---------------------------------------------------------------------------
// Kernel 1: pack masks[b, 1..15, hw] -> 15-bit word per (b,hw); init g_acc.
// ---------------------------------------------------------------------------
__global__ void pack_kernel(const int* __restrict__ masks) {
    int idx = blockIdx.x * blockDim.x + threadIdx.x;   // 0 .. B*HW-1
    if (idx < BB * CC * NM) g_acc[idx] = ORD_NEGINF;
    int b = idx / HWTOT;
    int hw = idx - b * HWTOT;
    const int* mp = masks + (size_t)b * MMASKS * HWTOT + hw;
    unsigned int bits = 0;
#pragma unroll
    for (int m = 1; m < MMASKS; ++m)
        bits |= (mp[(size_t)m * HWTOT] != 0 ? 1u : 0u) << (m - 1);
    g_bits[idx] = bits;
}

// ---------------------------------------------------------------------------
// Kernel 2: main masked-max. CTA = (chunk, b), 128 threads (warp = 32 channels).
// Transposed smem staging so mask bits are warp-uniform scalars.
// ---------------------------------------------------------------------------
__global__ void __launch_bounds__(128, 4) main_kernel(const float* __restrict__ enc) {
    __shared__ float tile[CC][TPAD];
    __shared__ unsigned int sbits[CHUNK];

    const int b    = blockIdx.y;
    const int pos0 = blockIdx.x * CHUNK;
    const int tid  = threadIdx.x;
    const int w    = tid >> 5;
    const int lane = tid & 31;
    const int rsub = lane >> 3;   // row sub-offset within 4-row group
    const int q    = lane & 7;    // 16B quad within 128B row

    // Stage the chunk's packed bits once (read-only afterwards).
    for (int i = tid; i < CHUNK; i += 128)
        sbits[i] = g_bits[b * HWTOT + pos0 + i];
    __syncthreads();

    const float* base = enc + (size_t)b * CC * HWTOT + pos0;

    // Register-staged prefetch of tile 0.
    // Warp w owns channel rows [32w, 32w+32): 8x float4 per thread, coalesced
    // (each LDG.128 covers 4 rows x 128B contiguous segments).
    float4 stage[8];
#pragma unroll
    for (int k = 0; k < 8; ++k) {
        int r = 32 * w + 4 * k + rsub;
        stage[k] = *reinterpret_cast<const float4*>(base + (size_t)r * HWTOT + q * 4);
    }

    const float NEGINF = __int_as_float(0xFF800000);
    float vmax[NM];
#pragma unroll
    for (int m = 0; m < NM; ++m) vmax[m] = NEGINF;

    const int c = 32 * w + lane;   // channel this lane accumulates

    for (int t = 0; t < NTILE; ++t) {
        // STS staged tile (stride-33 rows: conflict-free; warp-private rows).
#pragma unroll
        for (int k = 0; k < 8; ++k) {
            int r = 32 * w + 4 * k + rsub;
            float4 v = stage[k];
            tile[r][q * 4 + 0] = v.x;
            tile[r][q * 4 + 1] = v.y;
            tile[r][q * 4 + 2] = v.z;
            tile[r][q * 4 + 3] = v.w;
        }
        __syncwarp();

        // Prefetch next tile while computing this one.
        if (t + 1 < NTILE) {
#pragma unroll
            for (int k = 0; k < 8; ++k) {
                int r = 32 * w + 4 * k + rsub;
                stage[k] = *reinterpret_cast<const float4*>(
                    base + (size_t)r * HWTOT + (t + 1) * TILE + q * 4);
            }
        }

        const unsigned int* bt = sbits + t * TILE;
#pragma unroll 8
        for (int p = 0; p < TILE; ++p) {
            float val = tile[c][p];                 // column LDS, conflict-free
            unsigned int bits = bt[p];              // warp-uniform broadcast
#pragma unroll
            for (int m = 0; m < NM; ++m)
                if (bits & (1u << m)) vmax[m] = fmaxf(vmax[m], val);
        }
        __syncwarp();
    }

    // Cross-chunk reduction: order-mapped atomic max.
    unsigned int* acc = g_acc + (size_t)(b * CC + c) * NM;
#pragma unroll
    for (int m = 0; m < NM; ++m)
        atomicMax(acc + m, f2ord(vmax[m]));
}

// ---------------------------------------------------------------------------
// Kernel 3: decode accumulators into the output layout [B, C, 15, 1].
// ---------------------------------------------------------------------------
__global__ void decode_kernel(float* __restrict__ out) {
    int i = blockIdx.x * blockDim.x + threadIdx.x;
    if (i < BB * CC * NM) out[i] = ord2f(g_acc[i]);
}

// ---------------------------------------------------------------------------
extern "C" void kernel_launch(void* const* d_in, const int* in_sizes, int n_in,
                              void* d_out, int out_size) {
    const float* enc   = (const float*)d_in[0];
    const int*   masks = (const int*)d_in[1];
    float*       out   = (float*)d_out;

    pack_kernel<<<(BB * HWTOT) / 256, 256>>>(masks);
    main_kernel<<<dim3(NCHUNK, BB), 128>>>(enc);
    decode_kernel<<<(BB * CC * NM + 255) / 256, 256>>>(out);
}

// round 3
// speedup vs baseline: 1.4215x; 1.4215x over previous
#include <cuda_runtime.h>
#include <cuda_fp16.h>
#include <cstdint>

// Problem shape (fixed by the dataset):
//   encoded: [B=8, C=128, H=128, W=128] fp32
//   masks:   [B=8, M=16, H, W] int32 (0/1), channel 0 dropped
//   out:     [B, C, 15, 1] fp32 = masked spatial max per region
#define BB      8
#define CC      128
#define HWTOT   16384
#define NM      15
#define NCHUNK  64
#define CHUNK   (HWTOT / NCHUNK)   // 256 positions per CTA
#define TILEP   128                // positions per smem tile (2 tiles/chunk)
#define STRIDE  129                // pad: conflict-free column access
#define NPR     64                 // pair-rows: pr pairs channels (pr, pr+64)

// Scratch: per-chunk partial maxima, [b][c][m][chunk] fp32.
__device__ float g_part[BB * CC * NM * NCHUNK];   // 3.93 MB

__device__ __forceinline__ uint32_t h2pack(float lo, float hi) {
    __half2 h = __floats2half2_rn(lo, hi);   // lo -> .x (low), hi -> .y (high)
    return *reinterpret_cast<uint32_t*>(&h);
}

// ---------------------------------------------------------------------------
// Main kernel: CTA = (chunk, b), 128 threads / 4 warps.
//  - builds packed mask bits for its 256 positions from masks directly
//  - stages encoded as half2(c, c+64) pairs in transposed smem tiles
//  - 15 predicated HMNMX2 updates per (position, warp) covering 64 channels
// ---------------------------------------------------------------------------
__global__ void __launch_bounds__(128) main_kernel(const float* __restrict__ enc,
                                                   const int* __restrict__ masks) {
    __shared__ uint32_t htile[NPR * STRIDE];      // 33 KB
    __shared__ uint32_t sbits[CHUNK];             // 1 KB
    __shared__ uint32_t red[2 * 32 * NM];         // 3.75 KB

    const int b     = blockIdx.y;
    const int chunk = blockIdx.x;
    const int pos0  = chunk * CHUNK;
    const int tid   = threadIdx.x;
    const int w     = tid >> 5;
    const int lane  = tid & 31;
    const int rsub  = lane >> 3;    // 4-row group offset
    const int q     = lane & 7;     // 16B quad within 128B row segment

    // --- Packed mask bits: 2 positions per thread, 15 coalesced int2 loads ---
    {
        const int* mbase = masks + (size_t)b * 16 * HWTOT + pos0 + 2 * tid;
        uint32_t b0 = 0, b1 = 0;
#pragma unroll
        for (int m = 1; m < 16; ++m) {
            int2 v = *reinterpret_cast<const int2*>(mbase + (size_t)m * HWTOT);
            b0 |= (v.x != 0 ? 1u : 0u) << (m - 1);
            b1 |= (v.y != 0 ? 1u : 0u) << (m - 1);
        }
        sbits[2 * tid]     = b0;
        sbits[2 * tid + 1] = b1;
    }

    const float* ebase = enc + (size_t)b * CC * HWTOT + pos0;

    const uint32_t NEGINF2 = 0xFC00FC00u;   // packed fp16 -inf | -inf
    __half2 vmax[NM];
#pragma unroll
    for (int m = 0; m < NM; ++m)
        vmax[m] = *reinterpret_cast<const __half2*>(&NEGINF2);

    const int pr    = (w & 1) * 32 + lane;   // this warp's pair-row in compute
    const int pbase = (w >> 1) * 64;         // this warp's position half of a tile

    for (int t = 0; t < CHUNK / TILEP; ++t) {
        const int tb = t * TILEP;

        // --- Stage tile: warp w fills pair-rows [16w, 16w+16). Fully
        // coalesced LDG.128 (4 rows x 128B per instr), conflict-free STS. ---
#pragma unroll
        for (int j = 0; j < 4; ++j) {
#pragma unroll
            for (int k = 0; k < 4; ++k) {
                const int r    = 16 * w + 4 * k + rsub;     // pair-row
                const int lpos = 32 * j + 4 * q;            // pos within tile
                float4 lo = *reinterpret_cast<const float4*>(
                    ebase + (size_t)r * HWTOT + tb + lpos);
                float4 hi = *reinterpret_cast<const float4*>(
                    ebase + (size_t)(r + 64) * HWTOT + tb + lpos);
                uint32_t* d = htile + r * STRIDE + lpos;
                d[0] = h2pack(lo.x, hi.x);
                d[1] = h2pack(lo.y, hi.y);
                d[2] = h2pack(lo.z, hi.z);
                d[3] = h2pack(lo.w, hi.w);
            }
        }
        __syncthreads();

        // --- Compute: 64 positions per warp, 15 masked-max updates each.
        // bits is warp-uniform; (bits & const) != 0 should compile to
        // LOP3 with predicate destination + @P HMNMX2. ---
        const uint32_t* row = htile + pr * STRIDE;
        const uint32_t* bt  = sbits + tb;
#pragma unroll 4
        for (int p = pbase; p < pbase + 64; ++p) {
            const uint32_t bits = bt[p];     // warp-uniform broadcast LDS
            const uint32_t vr   = row[p];    // conflict-free column LDS
            const __half2  v2   = *reinterpret_cast<const __half2*>(&vr);
#pragma unroll
            for (int m = 0; m < NM; ++m)
                if (bits & (1u << m)) vmax[m] = __hmax2(vmax[m], v2);
        }
        __syncthreads();
    }

    // --- Intra-CTA reduce: warps 2,3 fold into warps 0,1 (same pr) ---
    if (w >= 2) {
#pragma unroll
        for (int m = 0; m < NM; ++m)
            red[((w & 1) * 32 + lane) * NM + m] =
                *reinterpret_cast<uint32_t*>(&vmax[m]);
    }
    __syncthreads();
    if (w < 2) {
#pragma unroll
        for (int m = 0; m < NM; ++m) {
            uint32_t o = red[(w * 32 + lane) * NM + m];
            vmax[m] = __hmax2(vmax[m], *reinterpret_cast<const __half2*>(&o));
        }
        // --- Write partials: channels pr (low half) and pr+64 (high half) ---
        float* plo = g_part + ((size_t)(b * CC + pr) * NM) * NCHUNK + chunk;
        float* phi = g_part + ((size_t)(b * CC + pr + 64) * NM) * NCHUNK + chunk;
#pragma unroll
        for (int m = 0; m < NM; ++m) {
            plo[m * NCHUNK] = __low2float(vmax[m]);
            phi[m * NCHUNK] = __high2float(vmax[m]);
        }
    }
}

// ---------------------------------------------------------------------------
// Reduce kernel: out[i] = max over 64 chunk partials (contiguous float4 reads).
// ---------------------------------------------------------------------------
__global__ void reduce_kernel(float* __restrict__ out) {
    const int i = blockIdx.x * blockDim.x + threadIdx.x;
    if (i >= BB * CC * NM) return;
    const float4* p = reinterpret_cast<const float4*>(g_part + (size_t)i * NCHUNK);
    float m = __int_as_float(0xFF800000);
#pragma unroll
    for (int k = 0; k < NCHUNK / 4; ++k) {
        float4 v = p[k];
        m = fmaxf(m, fmaxf(fmaxf(v.x, v.y), fmaxf(v.z, v.w)));
    }
    out[i] = m;
}

// ---------------------------------------------------------------------------
extern "C" void kernel_launch(void* const* d_in, const int* in_sizes, int n_in,
                              void* d_out, int out_size) {
    const float* enc   = (const float*)d_in[0];
    const int*   masks = (const int*)d_in[1];
    float*       out   = (float*)d_out;

    main_kernel<<<dim3(NCHUNK, BB), 128>>>(enc, masks);
    reduce_kernel<<<(BB * CC * NM + 255) / 256, 256>>>(out);
}